// round 5
// baseline (speedup 1.0000x reference)
#include <cuda_runtime.h>

#define NN 50000
#define NE 800000
#define D  64
#define NL 3
#define DCAT (D + NL * D)   // 256

typedef unsigned long long ull;

// ---------------- scratch (device globals) ----------------------------------
__device__ int   g_cnt1[NN], g_cnt2[NN], g_cur1[NN], g_cur2[NN];
__device__ int   g_off1[NN + 1], g_off2[NN + 1];
__device__ int   g_nbr1[NE], g_nbr2[NE];
__device__ __align__(16) float g_h[NN * D];
__device__ __align__(16) float g_s1[NN * D];
__device__ __align__(16) float g_s2[NN * D];
__device__ __align__(16) float g_cat[NN * DCAT];

__device__ __forceinline__ int clampi(int v) {
    return v < 0 ? 0 : (v >= NN ? NN - 1 : v);
}

// ---------------- packed f32x2 helpers (Blackwell) ---------------------------
__device__ __forceinline__ void fadd2(ull& a, ull b) {
    asm("add.rn.f32x2 %0, %0, %1;" : "+l"(a) : "l"(b));
}
__device__ __forceinline__ void ffma2(ull& a, ull x, ull w) {
    asm("fma.rn.f32x2 %0, %1, %2, %0;" : "+l"(a) : "l"(x), "l"(w));
}
__device__ __forceinline__ float2 unpack2(ull v) {
    float2 r; asm("mov.b64 {%0,%1}, %2;" : "=f"(r.x), "=f"(r.y) : "l"(v)); return r;
}
__device__ __forceinline__ ull pack2(float x, float y) {
    ull r; asm("mov.b64 %0, {%1,%2};" : "=l"(r) : "f"(x), "f"(y)); return r;
}

// ---------------- init: h = x, cat[:, :64] = x, zero CSR counters -----------
__global__ void k_init(const float* __restrict__ x) {
    int i = blockIdx.x * blockDim.x + threadIdx.x;
    if (i < NN * D) {
        float v = x[i];
        g_h[i] = v;
        g_cat[(i >> 6) * DCAT + (i & 63)] = v;
    }
    if (i < NN) {
        g_cnt1[i] = 0; g_cnt2[i] = 0;
        g_cur1[i] = 0; g_cur2[i] = 0;
    }
}

// ---------------- CSR build ---------------------------------------------------
__global__ void k_count(const int* __restrict__ ei) {
    int e = blockIdx.x * blockDim.x + threadIdx.x;
    if (e >= NE) return;
    int s = clampi(ei[e]);
    int d = clampi(ei[NE + e]);
    atomicAdd(&g_cnt1[d], 1);
    atomicAdd(&g_cnt2[s], 1);
}

__global__ void k_scan() {
    __shared__ int ssum1[1024], ssum2[1024];
    const int t  = threadIdx.x;
    const int CH = (NN + 1023) / 1024;
    const int base = t * CH;

    int s1 = 0, s2 = 0;
    for (int i = 0; i < CH; i++) {
        int n = base + i;
        if (n < NN) { s1 += g_cnt1[n]; s2 += g_cnt2[n]; }
    }
    ssum1[t] = s1; ssum2[t] = s2;
    __syncthreads();

    for (int off = 1; off < 1024; off <<= 1) {
        int a1 = ssum1[t], a2 = ssum2[t];
        int b1 = (t >= off) ? ssum1[t - off] : 0;
        int b2 = (t >= off) ? ssum2[t - off] : 0;
        __syncthreads();
        ssum1[t] = a1 + b1; ssum2[t] = a2 + b2;
        __syncthreads();
    }

    int ex1 = (t == 0) ? 0 : ssum1[t - 1];
    int ex2 = (t == 0) ? 0 : ssum2[t - 1];
    for (int i = 0; i < CH; i++) {
        int n = base + i;
        if (n < NN) {
            g_off1[n] = ex1; ex1 += g_cnt1[n];
            g_off2[n] = ex2; ex2 += g_cnt2[n];
        }
    }
    if (t == 0) {
        g_off1[NN] = ssum1[1023];
        g_off2[NN] = ssum2[1023];
    }
}

__global__ void k_fill(const int* __restrict__ ei) {
    int e = blockIdx.x * blockDim.x + threadIdx.x;
    if (e >= NE) return;
    int s = clampi(ei[e]);
    int d = clampi(ei[NE + e]);
    g_nbr1[g_off1[d] + atomicAdd(&g_cur1[d], 1)] = s;
    g_nbr2[g_off2[s] + atomicAdd(&g_cur2[s], 1)] = d;
}

// ---------------- gather-mean: 16 lanes/node, LDG.128, f32x2 accum ----------
__device__ __forceinline__ void gather16(const int* __restrict__ nbr,
                                         const ulonglong2* __restrict__ hv,
                                         int b, int e, int l16, unsigned mask,
                                         ull acc[4]) {
    for (int j0 = b; j0 < e; j0 += 16) {
        int m = e - j0; if (m > 16) m = 16;
        int idx = nbr[j0 + (l16 < m ? l16 : 0)];
        int jj = 0;
        for (; jj + 4 <= m; jj += 4) {
            int i0 = __shfl_sync(mask, idx, jj,     16);
            int i1 = __shfl_sync(mask, idx, jj + 1, 16);
            int i2 = __shfl_sync(mask, idx, jj + 2, 16);
            int i3 = __shfl_sync(mask, idx, jj + 3, 16);
            ulonglong2 v0 = hv[i0 * 16 + l16];
            ulonglong2 v1 = hv[i1 * 16 + l16];
            ulonglong2 v2 = hv[i2 * 16 + l16];
            ulonglong2 v3 = hv[i3 * 16 + l16];
            fadd2(acc[0], v0.x); fadd2(acc[1], v0.y);
            fadd2(acc[0], v1.x); fadd2(acc[1], v1.y);
            fadd2(acc[2], v2.x); fadd2(acc[3], v2.y);
            fadd2(acc[2], v3.x); fadd2(acc[3], v3.y);
        }
        for (; jj < m; jj++) {
            int i0 = __shfl_sync(mask, idx, jj, 16);
            ulonglong2 v0 = hv[i0 * 16 + l16];
            fadd2(acc[0], v0.x); fadd2(acc[1], v0.y);
        }
    }
}

// s1[n] = mean_{src -> n} h[src],  s2[n] = mean_{n -> dst} h[dst]
__global__ void k_agg() {
    const int tid  = threadIdx.x;
    const int l16  = tid & 15;
    const int n    = blockIdx.x * 16 + (tid >> 4);   // grid = 3125, exact
    const unsigned mask = 0xFFFFu << (tid & 0x10);
    const ulonglong2* __restrict__ hv = (const ulonglong2*)g_h;

    int b1 = g_off1[n], e1 = g_off1[n + 1];
    ull a[4] = {0, 0, 0, 0};
    gather16(g_nbr1, hv, b1, e1, l16, mask, a);
    fadd2(a[0], a[2]); fadd2(a[1], a[3]);
    float inv1 = 1.0f / (float)max(e1 - b1, 1);
    float2 lo = unpack2(a[0]), hi = unpack2(a[1]);
    ((float4*)g_s1)[n * 16 + l16] =
        make_float4(lo.x * inv1, lo.y * inv1, hi.x * inv1, hi.y * inv1);

    int b2 = g_off2[n], e2 = g_off2[n + 1];
    ull c[4] = {0, 0, 0, 0};
    gather16(g_nbr2, hv, b2, e2, l16, mask, c);
    fadd2(c[0], c[2]); fadd2(c[1], c[3]);
    float inv2 = 1.0f / (float)max(e2 - b2, 1);
    float2 lo2 = unpack2(c[0]), hi2 = unpack2(c[1]);
    ((float4*)g_s2)[n * 16 + l16] =
        make_float4(lo2.x * inv2, lo2.y * inv2, hi2.x * inv2, hi2.y * inv2);
}

// ---------------- fused layer GEMM (f32x2): h=relu([h,s1,s2]@W^T + b) -------
#define LT 5
#define KL 192                                     // 3 * 64
#define LAYER_SMEM (KL * 16 * 16 + 16 * (KL + 1) * 8)   // 49152 + 24704 = 73856
__global__ void k_layer(const float* __restrict__ w1, const float* __restrict__ w2,
                        const float* __restrict__ wr, const float* __restrict__ rb,
                        int l) {
    extern __shared__ char sm[];
    float*       swf = (float*)sm;                  // [k][cq] float4-view
    ulonglong2*  swu = (ulonglong2*)sm;
    ull*         sxu = (ull*)(sm + KL * 16 * 16);   // [16][KL+1] duplicated f32x2
    const int tid = threadIdx.x;

    // weights transposed: swf[(kg*16+cq)*4 + j] = W_src[4cq+j][k], kg = src*64+k
    for (int s = 0; s < 3; s++) {
        const float* w = (s == 0) ? wr : (s == 1) ? w1 : w2;
        for (int i = tid; i < 64 * 64; i += 256) {
            int c = i >> 6, k = i & 63;
            swf[((s * 64 + k) * 16 + (c >> 2)) * 4 + (c & 3)] = w[i];
        }
    }
    const int n_l = tid >> 4, cq = tid & 15;
    float4 bv = ((const float4*)rb)[cq];
    const ull bias0 = pack2(bv.x, bv.y), bias1 = pack2(bv.z, bv.w);

    for (int t = 0; t < LT; t++) {
        int node0 = (blockIdx.x * LT + t) * 16;
        __syncthreads();
        for (int i = tid; i < 16 * 48; i += 256) {     // float4 granularity
            int nl = i / 48, kq = i % 48;
            int node = node0 + nl;
            int src = kq >> 4, k4 = kq & 15;
            const float* xp = (src == 0) ? (g_h + node * D)
                            : (src == 1) ? (g_s1 + node * D)
                                         : (g_s2 + node * D);
            float4 v = ((const float4*)xp)[k4];
            ull* p = sxu + nl * (KL + 1) + kq * 4;
            p[0] = pack2(v.x, v.x); p[1] = pack2(v.y, v.y);
            p[2] = pack2(v.z, v.z); p[3] = pack2(v.w, v.w);
        }
        __syncthreads();

        ull a0 = bias0, a1 = bias1;
        const ull* __restrict__ xrow = sxu + n_l * (KL + 1);
#pragma unroll 16
        for (int k = 0; k < KL; k++) {
            ulonglong2 wv = swu[k * 16 + cq];
            ull xv = xrow[k];
            ffma2(a0, xv, wv.x);
            ffma2(a1, xv, wv.y);
        }
        float2 r0 = unpack2(a0), r1 = unpack2(a1);
        float4 hres = make_float4(fmaxf(r0.x, 0.f), fmaxf(r0.y, 0.f),
                                  fmaxf(r1.x, 0.f), fmaxf(r1.y, 0.f));
        int node = node0 + n_l;
        ((float4*)(g_h + node * D))[cq] = hres;
        ((float4*)(g_cat + node * DCAT + (l + 1) * D))[cq] = hres;
    }
}

// ---------------- final GEMM (f32x2): out = cat @ final_w^T + final_b -------
#define KF 256
#define FINAL_SMEM (KF * 16 * 16 + 16 * (KF + 1) * 8)  // 65536 + 32896 = 98432
__global__ void k_final(const float* __restrict__ fw, const float* __restrict__ fb,
                        float* __restrict__ out) {
    extern __shared__ char sm[];
    float*       swf = (float*)sm;
    ulonglong2*  swu = (ulonglong2*)sm;
    ull*         sxu = (ull*)(sm + KF * 16 * 16);
    const int tid = threadIdx.x;

    for (int i = tid; i < 64 * KF; i += 256) {
        int c = i >> 8, k = i & 255;
        swf[(k * 16 + (c >> 2)) * 4 + (c & 3)] = fw[i];
    }
    const int n_l = tid >> 4, cq = tid & 15;
    float4 bv = ((const float4*)fb)[cq];
    const ull bias0 = pack2(bv.x, bv.y), bias1 = pack2(bv.z, bv.w);

    for (int t = 0; t < LT; t++) {
        int node0 = (blockIdx.x * LT + t) * 16;
        __syncthreads();
        for (int i = tid; i < 16 * 64; i += 256) {     // 64 float4 per node
            int nl = i >> 6, k4 = i & 63;
            float4 v = ((const float4*)(g_cat + (node0 + nl) * DCAT))[k4];
            ull* p = sxu + nl * (KF + 1) + k4 * 4;
            p[0] = pack2(v.x, v.x); p[1] = pack2(v.y, v.y);
            p[2] = pack2(v.z, v.z); p[3] = pack2(v.w, v.w);
        }
        __syncthreads();

        ull a0 = bias0, a1 = bias1;
        const ull* __restrict__ xrow = sxu + n_l * (KF + 1);
#pragma unroll 16
        for (int k = 0; k < KF; k++) {
            ulonglong2 wv = swu[k * 16 + cq];
            ull xv = xrow[k];
            ffma2(a0, xv, wv.x);
            ffma2(a1, xv, wv.y);
        }
        float2 r0 = unpack2(a0), r1 = unpack2(a1);
        int node = node0 + n_l;
        ((float4*)(out + node * D))[cq] =
            make_float4(r0.x, r0.y, r1.x, r1.y);
    }
}

// ---------------- launch -----------------------------------------------------
extern "C" void kernel_launch(void* const* d_in, const int* in_sizes, int n_in,
                              void* d_out, int out_size) {
    const float* x     = (const float*)d_in[0];
    const int*   ei    = (const int*)d_in[1];
    const float* lin1  = (const float*)d_in[2];
    const float* lin2  = (const float*)d_in[3];
    const float* rootw = (const float*)d_in[4];
    const float* rootb = (const float*)d_in[5];
    const float* fw    = (const float*)d_in[6];
    const float* fb    = (const float*)d_in[7];
    float*       out   = (float*)d_out;

    cudaFuncSetAttribute(k_layer, cudaFuncAttributeMaxDynamicSharedMemorySize, LAYER_SMEM);
    cudaFuncSetAttribute(k_final, cudaFuncAttributeMaxDynamicSharedMemorySize, FINAL_SMEM);

    k_init <<<(NN * D + 255) / 256, 256>>>(x);
    k_count<<<(NE + 255) / 256, 256>>>(ei);
    k_scan <<<1, 1024>>>();
    k_fill <<<(NE + 255) / 256, 256>>>(ei);

    const int agg_grid  = NN / 16;                 // 3125, exact
    const int gemm_grid = NN / (16 * LT);          // 625, exact

    for (int l = 0; l < NL; l++) {
        k_agg  <<<agg_grid, 256>>>();
        k_layer<<<gemm_grid, 256, LAYER_SMEM>>>(lin1 + l * D * D, lin2 + l * D * D,
                                                rootw + l * D * D, rootb + l * D, l);
    }
    k_final<<<gemm_grid, 256, FINAL_SMEM>>>(fw, fb, out);
}

// round 6
// speedup vs baseline: 1.4872x; 1.4872x over previous
#include <cuda_runtime.h>

#define NN 50000
#define NE 800000
#define D  64
#define NL 3
#define DCAT (D + NL * D)   // 256

// ---------------- scratch (device globals) ----------------------------------
__device__ int   g_cnt1[NN], g_cnt2[NN], g_cur1[NN], g_cur2[NN];
__device__ int   g_off1[NN + 1], g_off2[NN + 1];
__device__ int   g_nbr1[NE], g_nbr2[NE];
__device__ __align__(16) float g_h[NN * D];
__device__ __align__(16) float g_s1[NN * D];
__device__ __align__(16) float g_s2[NN * D];
__device__ __align__(16) float g_cat[NN * DCAT];

__device__ __forceinline__ int clampi(int v) {
    return v < 0 ? 0 : (v >= NN ? NN - 1 : v);
}

// ---------------- init: h = x, cat[:, :64] = x, zero CSR counters -----------
__global__ void k_init(const float* __restrict__ x) {
    int i = blockIdx.x * blockDim.x + threadIdx.x;
    if (i < NN * D) {
        float v = x[i];
        g_h[i] = v;
        g_cat[(i >> 6) * DCAT + (i & 63)] = v;
    }
    if (i < NN) {
        g_cnt1[i] = 0; g_cnt2[i] = 0;
        g_cur1[i] = 0; g_cur2[i] = 0;
    }
}

// ---------------- CSR build ---------------------------------------------------
__global__ void k_count(const int* __restrict__ ei) {
    int e = blockIdx.x * blockDim.x + threadIdx.x;
    if (e >= NE) return;
    int s = clampi(ei[e]);
    int d = clampi(ei[NE + e]);
    atomicAdd(&g_cnt1[d], 1);
    atomicAdd(&g_cnt2[s], 1);
}

__global__ void k_scan() {
    __shared__ int ssum1[1024], ssum2[1024];
    const int t  = threadIdx.x;
    const int CH = (NN + 1023) / 1024;
    const int base = t * CH;

    int s1 = 0, s2 = 0;
    for (int i = 0; i < CH; i++) {
        int n = base + i;
        if (n < NN) { s1 += g_cnt1[n]; s2 += g_cnt2[n]; }
    }
    ssum1[t] = s1; ssum2[t] = s2;
    __syncthreads();

    for (int off = 1; off < 1024; off <<= 1) {
        int a1 = ssum1[t], a2 = ssum2[t];
        int b1 = (t >= off) ? ssum1[t - off] : 0;
        int b2 = (t >= off) ? ssum2[t - off] : 0;
        __syncthreads();
        ssum1[t] = a1 + b1; ssum2[t] = a2 + b2;
        __syncthreads();
    }

    int ex1 = (t == 0) ? 0 : ssum1[t - 1];
    int ex2 = (t == 0) ? 0 : ssum2[t - 1];
    for (int i = 0; i < CH; i++) {
        int n = base + i;
        if (n < NN) {
            g_off1[n] = ex1; ex1 += g_cnt1[n];
            g_off2[n] = ex2; ex2 += g_cnt2[n];
        }
    }
    if (t == 0) {
        g_off1[NN] = ssum1[1023];
        g_off2[NN] = ssum2[1023];
    }
}

__global__ void k_fill(const int* __restrict__ ei) {
    int e = blockIdx.x * blockDim.x + threadIdx.x;
    if (e >= NE) return;
    int s = clampi(ei[e]);
    int d = clampi(ei[NE + e]);
    g_nbr1[g_off1[d] + atomicAdd(&g_cur1[d], 1)] = s;
    g_nbr2[g_off2[s] + atomicAdd(&g_cur2[s], 1)] = d;
}

// ---------------- high-MLP directed gather-mean of h (R4, known-good) -------
__device__ __forceinline__ void gather_dir(const int* __restrict__ nbr,
                                           const float2* __restrict__ hv,
                                           int b, int e, int lane,
                                           float& ox, float& oy) {
    float ax = 0.f, ay = 0.f, bx = 0.f, by = 0.f;
    for (int j0 = b; j0 < e; j0 += 32) {
        int m = e - j0; if (m > 32) m = 32;
        int idx = nbr[j0 + (lane < m ? lane : 0)];
        int jj = 0;
        for (; jj + 4 <= m; jj += 4) {
            int i0 = __shfl_sync(0xffffffffu, idx, jj);
            int i1 = __shfl_sync(0xffffffffu, idx, jj + 1);
            int i2 = __shfl_sync(0xffffffffu, idx, jj + 2);
            int i3 = __shfl_sync(0xffffffffu, idx, jj + 3);
            float2 v0 = hv[i0 * 32 + lane];
            float2 v1 = hv[i1 * 32 + lane];
            float2 v2 = hv[i2 * 32 + lane];
            float2 v3 = hv[i3 * 32 + lane];
            ax += v0.x + v1.x; ay += v0.y + v1.y;
            bx += v2.x + v3.x; by += v2.y + v3.y;
        }
        for (; jj < m; jj++) {
            int i0 = __shfl_sync(0xffffffffu, idx, jj);
            float2 v0 = hv[i0 * 32 + lane];
            ax += v0.x; ay += v0.y;
        }
    }
    ox = ax + bx; oy = ay + by;
}

__global__ void k_agg() {
    int gw   = (blockIdx.x * blockDim.x + threadIdx.x) >> 5;
    int lane = threadIdx.x & 31;
    if (gw >= NN) return;
    const int n = gw;
    const float2* __restrict__ hv = (const float2*)g_h;

    int b1 = g_off1[n], e1 = g_off1[n + 1];
    float ax, ay;
    gather_dir(g_nbr1, hv, b1, e1, lane, ax, ay);
    float inv1 = 1.0f / (float)max(e1 - b1, 1);

    int b2 = g_off2[n], e2 = g_off2[n + 1];
    float cx, cy;
    gather_dir(g_nbr2, hv, b2, e2, lane, cx, cy);
    float inv2 = 1.0f / (float)max(e2 - b2, 1);

    ((float2*)g_s1)[n * 32 + lane] = make_float2(ax * inv1, ay * inv1);
    ((float2*)g_s2)[n * 32 + lane] = make_float2(cx * inv2, cy * inv2);
}

// -------- layer GEMM v3: thread = (slot,c), 4 nodes/thread, 16 FMA per w-load
#define LT 5
#define LAYER_SMEM ((64 * 49 + 16 * 48) * (int)sizeof(float4))   // 62464 B
__global__ void __launch_bounds__(256) k_layer(
        const float* __restrict__ w1, const float* __restrict__ w2,
        const float* __restrict__ wr, const float* __restrict__ rb, int l) {
    extern __shared__ float4 dsm[];
    float4* sw4 = dsm;                   // [c][kq], padded stride 49
    float4* sx4 = dsm + 64 * 49;         // [nl][kq], nl = 0..15
    const int tid = threadIdx.x;

    // weights, native [c][k]; k-order: quads 0-15 Wr, 16-31 W1, 32-47 W2
    for (int i4 = tid; i4 < 64 * 48; i4 += 256) {
        int c = i4 / 48, kq = i4 % 48;
        int src = kq >> 4, kk4 = kq & 15;
        const float* w = (src == 0) ? wr : (src == 1) ? w1 : w2;
        sw4[c * 49 + kq] = ((const float4*)w)[c * 16 + kk4];
    }

    const int slot = tid >> 6;           // 0..3 -> nodes slot*4 .. slot*4+3
    const int c    = tid & 63;
    const float bias = rb[c];

    for (int t = 0; t < LT; t++) {
        int node0 = (blockIdx.x * LT + t) * 16;
        __syncthreads();
        for (int i4 = tid; i4 < 16 * 48; i4 += 256) {
            int nl = i4 / 48, kq = i4 % 48;
            int src = kq >> 4, kk4 = kq & 15;
            int node = node0 + nl;
            const float* xp = (src == 0) ? (g_h + node * D)
                            : (src == 1) ? (g_s1 + node * D)
                                         : (g_s2 + node * D);
            sx4[nl * 48 + kq] = ((const float4*)xp)[kk4];
        }
        __syncthreads();

        float acc0 = bias, acc1 = bias, acc2 = bias, acc3 = bias;
        const float4* __restrict__ xr = sx4 + slot * 4 * 48;
#pragma unroll 8
        for (int kq = 0; kq < 48; kq++) {
            float4 wv = sw4[c * 49 + kq];
            float4 x0 = xr[kq];
            float4 x1 = xr[48 + kq];
            float4 x2 = xr[96 + kq];
            float4 x3 = xr[144 + kq];
            acc0 = fmaf(x0.x, wv.x, acc0); acc0 = fmaf(x0.y, wv.y, acc0);
            acc0 = fmaf(x0.z, wv.z, acc0); acc0 = fmaf(x0.w, wv.w, acc0);
            acc1 = fmaf(x1.x, wv.x, acc1); acc1 = fmaf(x1.y, wv.y, acc1);
            acc1 = fmaf(x1.z, wv.z, acc1); acc1 = fmaf(x1.w, wv.w, acc1);
            acc2 = fmaf(x2.x, wv.x, acc2); acc2 = fmaf(x2.y, wv.y, acc2);
            acc2 = fmaf(x2.z, wv.z, acc2); acc2 = fmaf(x2.w, wv.w, acc2);
            acc3 = fmaf(x3.x, wv.x, acc3); acc3 = fmaf(x3.y, wv.y, acc3);
            acc3 = fmaf(x3.z, wv.z, acc3); acc3 = fmaf(x3.w, wv.w, acc3);
        }
        int nb = node0 + slot * 4;
        float r0 = fmaxf(acc0, 0.f), r1 = fmaxf(acc1, 0.f);
        float r2 = fmaxf(acc2, 0.f), r3 = fmaxf(acc3, 0.f);
        g_h[(nb + 0) * D + c] = r0;
        g_h[(nb + 1) * D + c] = r1;
        g_h[(nb + 2) * D + c] = r2;
        g_h[(nb + 3) * D + c] = r3;
        int cb = (l + 1) * D + c;
        g_cat[(nb + 0) * DCAT + cb] = r0;
        g_cat[(nb + 1) * DCAT + cb] = r1;
        g_cat[(nb + 2) * DCAT + cb] = r2;
        g_cat[(nb + 3) * DCAT + cb] = r3;
    }
}

// -------- final GEMM v3: out = cat @ final_w^T + final_b --------------------
#define FINAL_SMEM ((64 * 65 + 16 * 64) * (int)sizeof(float4))   // 82944 B
__global__ void __launch_bounds__(256) k_final(
        const float* __restrict__ fw, const float* __restrict__ fb,
        float* __restrict__ out) {
    extern __shared__ float4 dsm[];
    float4* sw4 = dsm;                   // [c][kq], padded stride 65
    float4* sx4 = dsm + 64 * 65;         // [nl][kq]
    const int tid = threadIdx.x;

    for (int i4 = tid; i4 < 64 * 64; i4 += 256) {
        int c = i4 >> 6, kq = i4 & 63;
        sw4[c * 65 + kq] = ((const float4*)fw)[c * 64 + kq];
    }

    const int slot = tid >> 6;
    const int c    = tid & 63;
    const float bias = fb[c];

    for (int t = 0; t < LT; t++) {
        int node0 = (blockIdx.x * LT + t) * 16;
        __syncthreads();
        for (int i4 = tid; i4 < 16 * 64; i4 += 256) {
            int nl = i4 >> 6, kq = i4 & 63;
            sx4[i4] = ((const float4*)(g_cat + (node0 + nl) * DCAT))[kq];
        }
        __syncthreads();

        float acc0 = bias, acc1 = bias, acc2 = bias, acc3 = bias;
        const float4* __restrict__ xr = sx4 + slot * 4 * 64;
#pragma unroll 8
        for (int kq = 0; kq < 64; kq++) {
            float4 wv = sw4[c * 65 + kq];
            float4 x0 = xr[kq];
            float4 x1 = xr[64 + kq];
            float4 x2 = xr[128 + kq];
            float4 x3 = xr[192 + kq];
            acc0 = fmaf(x0.x, wv.x, acc0); acc0 = fmaf(x0.y, wv.y, acc0);
            acc0 = fmaf(x0.z, wv.z, acc0); acc0 = fmaf(x0.w, wv.w, acc0);
            acc1 = fmaf(x1.x, wv.x, acc1); acc1 = fmaf(x1.y, wv.y, acc1);
            acc1 = fmaf(x1.z, wv.z, acc1); acc1 = fmaf(x1.w, wv.w, acc1);
            acc2 = fmaf(x2.x, wv.x, acc2); acc2 = fmaf(x2.y, wv.y, acc2);
            acc2 = fmaf(x2.z, wv.z, acc2); acc2 = fmaf(x2.w, wv.w, acc2);
            acc3 = fmaf(x3.x, wv.x, acc3); acc3 = fmaf(x3.y, wv.y, acc3);
            acc3 = fmaf(x3.z, wv.z, acc3); acc3 = fmaf(x3.w, wv.w, acc3);
        }
        int nb = node0 + slot * 4;
        out[(nb + 0) * D + c] = acc0;
        out[(nb + 1) * D + c] = acc1;
        out[(nb + 2) * D + c] = acc2;
        out[(nb + 3) * D + c] = acc3;
    }
}

// ---------------- launch -----------------------------------------------------
extern "C" void kernel_launch(void* const* d_in, const int* in_sizes, int n_in,
                              void* d_out, int out_size) {
    const float* x     = (const float*)d_in[0];
    const int*   ei    = (const int*)d_in[1];
    const float* lin1  = (const float*)d_in[2];
    const float* lin2  = (const float*)d_in[3];
    const float* rootw = (const float*)d_in[4];
    const float* rootb = (const float*)d_in[5];
    const float* fw    = (const float*)d_in[6];
    const float* fb    = (const float*)d_in[7];
    float*       out   = (float*)d_out;

    cudaFuncSetAttribute(k_layer, cudaFuncAttributeMaxDynamicSharedMemorySize, LAYER_SMEM);
    cudaFuncSetAttribute(k_final, cudaFuncAttributeMaxDynamicSharedMemorySize, FINAL_SMEM);

    k_init <<<(NN * D + 255) / 256, 256>>>(x);
    k_count<<<(NE + 255) / 256, 256>>>(ei);
    k_scan <<<1, 1024>>>();
    k_fill <<<(NE + 255) / 256, 256>>>(ei);

    const int agg_grid  = (NN * 32 + 255) / 256;
    const int gemm_grid = NN / (16 * LT);          // 625, exact

    for (int l = 0; l < NL; l++) {
        k_agg  <<<agg_grid, 256>>>();
        k_layer<<<gemm_grid, 256, LAYER_SMEM>>>(lin1 + l * D * D, lin2 + l * D * D,
                                                rootw + l * D * D, rootb + l * D, l);
    }
    k_final<<<gemm_grid, 256, FINAL_SMEM>>>(fw, fb, out);
}

// round 7
// speedup vs baseline: 1.6372x; 1.1009x over previous
#include <cuda_runtime.h>

#define NN 50000
#define NE 800000
#define D  64
#define NL 3
#define DCAT (D + NL * D)   // 256

// ---------------- scratch (device globals) ----------------------------------
__device__ int   g_cnt1[NN], g_cnt2[NN], g_cur1[NN], g_cur2[NN];
__device__ int   g_off1[NN + 1], g_off2[NN + 1];
__device__ int   g_nbr1[NE], g_nbr2[NE];
__device__ __align__(16) float g_h[NN * D];
__device__ __align__(16) float g_s1[NN * D];
__device__ __align__(16) float g_s2[NN * D];
__device__ __align__(16) float g_cat[NN * DCAT];

__device__ __forceinline__ int clampi(int v) {
    return v < 0 ? 0 : (v >= NN ? NN - 1 : v);
}

// ---------------- init -------------------------------------------------------
__global__ void k_init(const float* __restrict__ x) {
    int i = blockIdx.x * blockDim.x + threadIdx.x;
    if (i < NN * D) {
        float v = x[i];
        g_h[i] = v;
        g_cat[(i >> 6) * DCAT + (i & 63)] = v;
    }
    if (i < NN) {
        g_cnt1[i] = 0; g_cnt2[i] = 0;
        g_cur1[i] = 0; g_cur2[i] = 0;
    }
}

// ---------------- CSR build ---------------------------------------------------
__global__ void k_count(const int* __restrict__ ei) {
    int e = blockIdx.x * blockDim.x + threadIdx.x;
    if (e >= NE) return;
    int s = clampi(ei[e]);
    int d = clampi(ei[NE + e]);
    atomicAdd(&g_cnt1[d], 1);
    atomicAdd(&g_cnt2[s], 1);
}

__global__ void k_scan() {
    __shared__ int ssum1[1024], ssum2[1024];
    const int t  = threadIdx.x;
    const int CH = (NN + 1023) / 1024;
    const int base = t * CH;

    int s1 = 0, s2 = 0;
    for (int i = 0; i < CH; i++) {
        int n = base + i;
        if (n < NN) { s1 += g_cnt1[n]; s2 += g_cnt2[n]; }
    }
    ssum1[t] = s1; ssum2[t] = s2;
    __syncthreads();

    for (int off = 1; off < 1024; off <<= 1) {
        int a1 = ssum1[t], a2 = ssum2[t];
        int b1 = (t >= off) ? ssum1[t - off] : 0;
        int b2 = (t >= off) ? ssum2[t - off] : 0;
        __syncthreads();
        ssum1[t] = a1 + b1; ssum2[t] = a2 + b2;
        __syncthreads();
    }

    int ex1 = (t == 0) ? 0 : ssum1[t - 1];
    int ex2 = (t == 0) ? 0 : ssum2[t - 1];
    for (int i = 0; i < CH; i++) {
        int n = base + i;
        if (n < NN) {
            g_off1[n] = ex1; ex1 += g_cnt1[n];
            g_off2[n] = ex2; ex2 += g_cnt2[n];
        }
    }
    if (t == 0) {
        g_off1[NN] = ssum1[1023];
        g_off2[NN] = ssum2[1023];
    }
}

__global__ void k_fill(const int* __restrict__ ei) {
    int e = blockIdx.x * blockDim.x + threadIdx.x;
    if (e >= NE) return;
    int s = clampi(ei[e]);
    int d = clampi(ei[NE + e]);
    g_nbr1[g_off1[d] + atomicAdd(&g_cur1[d], 1)] = s;
    g_nbr2[g_off2[s] + atomicAdd(&g_cur2[s], 1)] = d;
}

// ---------------- high-MLP directed gather-mean (R4, known-good) -------------
__device__ __forceinline__ void gather_dir(const int* __restrict__ nbr,
                                           const float2* __restrict__ hv,
                                           int b, int e, int lane,
                                           float& ox, float& oy) {
    float ax = 0.f, ay = 0.f, bx = 0.f, by = 0.f;
    for (int j0 = b; j0 < e; j0 += 32) {
        int m = e - j0; if (m > 32) m = 32;
        int idx = nbr[j0 + (lane < m ? lane : 0)];
        int jj = 0;
        for (; jj + 4 <= m; jj += 4) {
            int i0 = __shfl_sync(0xffffffffu, idx, jj);
            int i1 = __shfl_sync(0xffffffffu, idx, jj + 1);
            int i2 = __shfl_sync(0xffffffffu, idx, jj + 2);
            int i3 = __shfl_sync(0xffffffffu, idx, jj + 3);
            float2 v0 = hv[i0 * 32 + lane];
            float2 v1 = hv[i1 * 32 + lane];
            float2 v2 = hv[i2 * 32 + lane];
            float2 v3 = hv[i3 * 32 + lane];
            ax += v0.x + v1.x; ay += v0.y + v1.y;
            bx += v2.x + v3.x; by += v2.y + v3.y;
        }
        for (; jj < m; jj++) {
            int i0 = __shfl_sync(0xffffffffu, idx, jj);
            float2 v0 = hv[i0 * 32 + lane];
            ax += v0.x; ay += v0.y;
        }
    }
    ox = ax + bx; oy = ay + by;
}

__global__ void k_agg() {
    int gw   = (blockIdx.x * blockDim.x + threadIdx.x) >> 5;
    int lane = threadIdx.x & 31;
    if (gw >= NN) return;
    const int n = gw;
    const float2* __restrict__ hv = (const float2*)g_h;

    int b1 = g_off1[n], e1 = g_off1[n + 1];
    float ax, ay;
    gather_dir(g_nbr1, hv, b1, e1, lane, ax, ay);
    float inv1 = 1.0f / (float)max(e1 - b1, 1);

    int b2 = g_off2[n], e2 = g_off2[n + 1];
    float cx, cy;
    gather_dir(g_nbr2, hv, b2, e2, lane, cx, cy);
    float inv2 = 1.0f / (float)max(e2 - b2, 1);

    ((float2*)g_s1)[n * 32 + lane] = make_float2(ax * inv1, ay * inv1);
    ((float2*)g_s2)[n * 32 + lane] = make_float2(cx * inv2, cy * inv2);
}

// ===== GEMM v4: thread = (node-group, col-quad); 4 nodes x 4 cols / thread ===
// weights transposed [k][c] in smem (stride 68); x rows broadcast as float4.
#define LT   5
#define TILE 64
#define KL   192
#define WST  68                      // w row stride (floats)
#define XST  49                      // x row stride (float4)
#define LAYER_SMEM ((KL * WST + TILE * XST * 4) * (int)sizeof(float))  // 102400

__global__ void __launch_bounds__(256) k_layer(
        const float* __restrict__ w1, const float* __restrict__ w2,
        const float* __restrict__ wr, const float* __restrict__ rb, int l) {
    extern __shared__ float sm[];
    float*  sw  = sm;                          // [192][68]
    float4* sx4 = (float4*)(sm + KL * WST);    // [64][49]
    const int tid = threadIdx.x;

    // transpose weights into [k][c]; k-order: 0-63 Wr, 64-127 W1, 128-191 W2
    for (int s = 0; s < 3; s++) {
        const float* w = (s == 0) ? wr : (s == 1) ? w1 : w2;
        for (int i = tid; i < 64 * 64; i += 256) {
            int c = i >> 6, k = i & 63;
            sw[(s * 64 + k) * WST + c] = w[i];
        }
    }
    const int grp = tid >> 4;                  // 0..15 -> nodes grp*4..grp*4+3
    const int cq  = tid & 15;                  // col quad
    const float4 bias = ((const float4*)rb)[cq];
    const float4* sw4 = (const float4*)sw;     // row stride 17 float4

    for (int t = 0; t < LT; t++) {
        int node0 = (blockIdx.x * LT + t) * TILE;
        __syncthreads();
        for (int i4 = tid; i4 < TILE * 48; i4 += 256) {
            int nl = i4 / 48, kq = i4 % 48;
            int src = kq >> 4, k4 = kq & 15;
            int node = node0 + nl; if (node >= NN) node = NN - 1;
            const float* xp = (src == 0) ? (g_h + node * D)
                            : (src == 1) ? (g_s1 + node * D)
                                         : (g_s2 + node * D);
            sx4[nl * XST + kq] = ((const float4*)xp)[k4];
        }
        __syncthreads();

        float4 a0 = bias, a1 = bias, a2 = bias, a3 = bias;
        const float4* xr = sx4 + grp * 4 * XST;
#pragma unroll 4
        for (int kq = 0; kq < 48; kq++) {
            float4 wv0 = sw4[(4 * kq + 0) * 17 + cq];
            float4 wv1 = sw4[(4 * kq + 1) * 17 + cq];
            float4 wv2 = sw4[(4 * kq + 2) * 17 + cq];
            float4 wv3 = sw4[(4 * kq + 3) * 17 + cq];
            float4 x0 = xr[kq];
            float4 x1 = xr[XST + kq];
            float4 x2 = xr[2 * XST + kq];
            float4 x3 = xr[3 * XST + kq];
#define STEP(A, X) \
            A.x = fmaf(X.x, wv0.x, A.x); A.y = fmaf(X.x, wv0.y, A.y); \
            A.z = fmaf(X.x, wv0.z, A.z); A.w = fmaf(X.x, wv0.w, A.w); \
            A.x = fmaf(X.y, wv1.x, A.x); A.y = fmaf(X.y, wv1.y, A.y); \
            A.z = fmaf(X.y, wv1.z, A.z); A.w = fmaf(X.y, wv1.w, A.w); \
            A.x = fmaf(X.z, wv2.x, A.x); A.y = fmaf(X.z, wv2.y, A.y); \
            A.z = fmaf(X.z, wv2.z, A.z); A.w = fmaf(X.z, wv2.w, A.w); \
            A.x = fmaf(X.w, wv3.x, A.x); A.y = fmaf(X.w, wv3.y, A.y); \
            A.z = fmaf(X.w, wv3.z, A.z); A.w = fmaf(X.w, wv3.w, A.w);
            STEP(a0, x0) STEP(a1, x1) STEP(a2, x2) STEP(a3, x3)
#undef STEP
        }
        int nb = node0 + grp * 4;
        int cb = (l + 1) * D;
#define EMIT(A, I) \
        if (nb + I < NN) { \
            float4 r = make_float4(fmaxf(A.x, 0.f), fmaxf(A.y, 0.f), \
                                   fmaxf(A.z, 0.f), fmaxf(A.w, 0.f)); \
            ((float4*)(g_h + (nb + I) * D))[cq] = r; \
            ((float4*)(g_cat + (nb + I) * DCAT + cb))[cq] = r; \
        }
        EMIT(a0, 0) EMIT(a1, 1) EMIT(a2, 2) EMIT(a3, 3)
#undef EMIT
    }
}

// ===== final GEMM v4: out = cat @ final_w^T + final_b =======================
#define KF 256
#define XSTF 65                     // x row stride (float4)
#define FINAL_SMEM ((KF * WST + TILE * XSTF * 4) * (int)sizeof(float))  // 136192

__global__ void __launch_bounds__(256) k_final(
        const float* __restrict__ fw, const float* __restrict__ fb,
        float* __restrict__ out) {
    extern __shared__ float sm[];
    float*  sw  = sm;                          // [256][68]
    float4* sx4 = (float4*)(sm + KF * WST);    // [64][65]
    const int tid = threadIdx.x;

    for (int i = tid; i < 64 * KF; i += 256) {
        int c = i >> 8, k = i & 255;
        sw[k * WST + c] = fw[i];
    }
    const int grp = tid >> 4;
    const int cq  = tid & 15;
    const float4 bias = ((const float4*)fb)[cq];
    const float4* sw4 = (const float4*)sw;

    for (int t = 0; t < LT; t++) {
        int node0 = (blockIdx.x * LT + t) * TILE;
        __syncthreads();
        for (int i4 = tid; i4 < TILE * 64; i4 += 256) {
            int nl = i4 >> 6, kq = i4 & 63;
            int node = node0 + nl; if (node >= NN) node = NN - 1;
            sx4[nl * XSTF + kq] = ((const float4*)(g_cat + node * DCAT))[kq];
        }
        __syncthreads();

        float4 a0 = bias, a1 = bias, a2 = bias, a3 = bias;
        const float4* xr = sx4 + grp * 4 * XSTF;
#pragma unroll 4
        for (int kq = 0; kq < 64; kq++) {
            float4 wv0 = sw4[(4 * kq + 0) * 17 + cq];
            float4 wv1 = sw4[(4 * kq + 1) * 17 + cq];
            float4 wv2 = sw4[(4 * kq + 2) * 17 + cq];
            float4 wv3 = sw4[(4 * kq + 3) * 17 + cq];
            float4 x0 = xr[kq];
            float4 x1 = xr[XSTF + kq];
            float4 x2 = xr[2 * XSTF + kq];
            float4 x3 = xr[3 * XSTF + kq];
#define STEP(A, X) \
            A.x = fmaf(X.x, wv0.x, A.x); A.y = fmaf(X.x, wv0.y, A.y); \
            A.z = fmaf(X.x, wv0.z, A.z); A.w = fmaf(X.x, wv0.w, A.w); \
            A.x = fmaf(X.y, wv1.x, A.x); A.y = fmaf(X.y, wv1.y, A.y); \
            A.z = fmaf(X.y, wv1.z, A.z); A.w = fmaf(X.y, wv1.w, A.w); \
            A.x = fmaf(X.z, wv2.x, A.x); A.y = fmaf(X.z, wv2.y, A.y); \
            A.z = fmaf(X.z, wv2.z, A.z); A.w = fmaf(X.z, wv2.w, A.w); \
            A.x = fmaf(X.w, wv3.x, A.x); A.y = fmaf(X.w, wv3.y, A.y); \
            A.z = fmaf(X.w, wv3.z, A.z); A.w = fmaf(X.w, wv3.w, A.w);
            STEP(a0, x0) STEP(a1, x1) STEP(a2, x2) STEP(a3, x3)
#undef STEP
        }
        int nb = node0 + grp * 4;
        if (nb + 0 < NN) ((float4*)(out + (nb + 0) * D))[cq] = a0;
        if (nb + 1 < NN) ((float4*)(out + (nb + 1) * D))[cq] = a1;
        if (nb + 2 < NN) ((float4*)(out + (nb + 2) * D))[cq] = a2;
        if (nb + 3 < NN) ((float4*)(out + (nb + 3) * D))[cq] = a3;
    }
}

// ---------------- launch -----------------------------------------------------
extern "C" void kernel_launch(void* const* d_in, const int* in_sizes, int n_in,
                              void* d_out, int out_size) {
    const float* x     = (const float*)d_in[0];
    const int*   ei    = (const int*)d_in[1];
    const float* lin1  = (const float*)d_in[2];
    const float* lin2  = (const float*)d_in[3];
    const float* rootw = (const float*)d_in[4];
    const float* rootb = (const float*)d_in[5];
    const float* fw    = (const float*)d_in[6];
    const float* fb    = (const float*)d_in[7];
    float*       out   = (float*)d_out;

    cudaFuncSetAttribute(k_layer, cudaFuncAttributeMaxDynamicSharedMemorySize, LAYER_SMEM);
    cudaFuncSetAttribute(k_final, cudaFuncAttributeMaxDynamicSharedMemorySize, FINAL_SMEM);

    k_init <<<(NN * D + 255) / 256, 256>>>(x);
    k_count<<<(NE + 255) / 256, 256>>>(ei);
    k_scan <<<1, 1024>>>();
    k_fill <<<(NE + 255) / 256, 256>>>(ei);

    const int agg_grid  = (NN * 32 + 255) / 256;
    const int gemm_grid = (NN + LT * TILE - 1) / (LT * TILE);   // 157

    for (int l = 0; l < NL; l++) {
        k_agg  <<<agg_grid, 256>>>();
        k_layer<<<gemm_grid, 256, LAYER_SMEM>>>(lin1 + l * D * D, lin2 + l * D * D,
                                                rootw + l * D * D, rootb + l * D, l);
    }
    k_final<<<gemm_grid, 256, FINAL_SMEM>>>(fw, fb, out);
}

// round 8
// speedup vs baseline: 1.6837x; 1.0284x over previous
#include <cuda_runtime.h>

#define NN 50000
#define NE 800000
#define D  64
#define NL 3
#define DCAT (D + NL * D)   // 256

// ---------------- scratch (device globals) ----------------------------------
__device__ int   g_cnt1[NN], g_cnt2[NN], g_cur1[NN], g_cur2[NN];
__device__ int   g_off1[NN + 1], g_off2[NN + 1];
__device__ int   g_nbr1[NE], g_nbr2[NE];
__device__ __align__(16) float g_h[NN * D];
__device__ __align__(16) float g_s1[NN * D];
__device__ __align__(16) float g_s2[NN * D];
__device__ __align__(16) float g_cat[NN * DCAT];

__device__ __forceinline__ int clampi(int v) {
    return v < 0 ? 0 : (v >= NN ? NN - 1 : v);
}

// ---------------- init -------------------------------------------------------
__global__ void k_init(const float* __restrict__ x) {
    int i = blockIdx.x * blockDim.x + threadIdx.x;
    if (i < NN * D) {
        float v = x[i];
        g_h[i] = v;
        g_cat[(i >> 6) * DCAT + (i & 63)] = v;
    }
    if (i < NN) {
        g_cnt1[i] = 0; g_cnt2[i] = 0;
        g_cur1[i] = 0; g_cur2[i] = 0;
    }
}

// ---------------- CSR build ---------------------------------------------------
__global__ void k_count(const int* __restrict__ ei) {
    int e = blockIdx.x * blockDim.x + threadIdx.x;
    if (e >= NE) return;
    int s = clampi(ei[e]);
    int d = clampi(ei[NE + e]);
    atomicAdd(&g_cnt1[d], 1);
    atomicAdd(&g_cnt2[s], 1);
}

__global__ void k_scan() {
    __shared__ int ssum1[1024], ssum2[1024];
    const int t  = threadIdx.x;
    const int CH = (NN + 1023) / 1024;
    const int base = t * CH;

    int s1 = 0, s2 = 0;
    for (int i = 0; i < CH; i++) {
        int n = base + i;
        if (n < NN) { s1 += g_cnt1[n]; s2 += g_cnt2[n]; }
    }
    ssum1[t] = s1; ssum2[t] = s2;
    __syncthreads();

    for (int off = 1; off < 1024; off <<= 1) {
        int a1 = ssum1[t], a2 = ssum2[t];
        int b1 = (t >= off) ? ssum1[t - off] : 0;
        int b2 = (t >= off) ? ssum2[t - off] : 0;
        __syncthreads();
        ssum1[t] = a1 + b1; ssum2[t] = a2 + b2;
        __syncthreads();
    }

    int ex1 = (t == 0) ? 0 : ssum1[t - 1];
    int ex2 = (t == 0) ? 0 : ssum2[t - 1];
    for (int i = 0; i < CH; i++) {
        int n = base + i;
        if (n < NN) {
            g_off1[n] = ex1; ex1 += g_cnt1[n];
            g_off2[n] = ex2; ex2 += g_cnt2[n];
        }
    }
    if (t == 0) {
        g_off1[NN] = ssum1[1023];
        g_off2[NN] = ssum2[1023];
    }
}

__global__ void k_fill(const int* __restrict__ ei) {
    int e = blockIdx.x * blockDim.x + threadIdx.x;
    if (e >= NE) return;
    int s = clampi(ei[e]);
    int d = clampi(ei[NE + e]);
    g_nbr1[g_off1[d] + atomicAdd(&g_cur1[d], 1)] = s;
    g_nbr2[g_off2[s] + atomicAdd(&g_cur2[s], 1)] = d;
}

// ======= agg v3: one LDG.128 gathers TWO neighbor rows (half-warp split) =====
__device__ __forceinline__ float4 gather_dir2(const int* __restrict__ nbr,
                                              const float4* __restrict__ hv,
                                              int b, int e, int lane,
                                              int half, int l16) {
    float4 a0 = make_float4(0.f, 0.f, 0.f, 0.f);
    float4 a1 = make_float4(0.f, 0.f, 0.f, 0.f);
    for (int j0 = b; j0 < e; j0 += 32) {
        int m = e - j0; if (m > 32) m = 32;
        int idx = nbr[j0 + (lane < m ? lane : 0)];   // coalesced, 32 indices
        int jj = 0;
        for (; jj + 8 <= m; jj += 8) {               // 8 neighbors = 4 LDG.128
            int i0 = __shfl_sync(0xffffffffu, idx, jj     + half);
            int i1 = __shfl_sync(0xffffffffu, idx, jj + 2 + half);
            int i2 = __shfl_sync(0xffffffffu, idx, jj + 4 + half);
            int i3 = __shfl_sync(0xffffffffu, idx, jj + 6 + half);
            float4 v0 = hv[i0 * 16 + l16];
            float4 v1 = hv[i1 * 16 + l16];
            float4 v2 = hv[i2 * 16 + l16];
            float4 v3 = hv[i3 * 16 + l16];
            a0.x += v0.x + v1.x; a0.y += v0.y + v1.y;
            a0.z += v0.z + v1.z; a0.w += v0.w + v1.w;
            a1.x += v2.x + v3.x; a1.y += v2.y + v3.y;
            a1.z += v2.z + v3.z; a1.w += v2.w + v3.w;
        }
        for (; jj < m; jj += 2) {                    // pair remainder
            int jsel = jj + half;
            int i0 = __shfl_sync(0xffffffffu, idx, jsel < m ? jsel : jj);
            float4 v0 = hv[i0 * 16 + l16];
            if (jsel < m) {
                a0.x += v0.x; a0.y += v0.y; a0.z += v0.z; a0.w += v0.w;
            }
        }
    }
    a0.x += a1.x; a0.y += a1.y; a0.z += a1.z; a0.w += a1.w;
    return a0;
}

__global__ void k_agg() {
    int gw   = (blockIdx.x * blockDim.x + threadIdx.x) >> 5;  // one warp / node
    int lane = threadIdx.x & 31;
    if (gw >= NN) return;
    const int n    = gw;
    const int half = lane >> 4;       // 0: even neighbors, 1: odd neighbors
    const int l16  = lane & 15;       // float4 column within row
    const float4* __restrict__ hv = (const float4*)g_h;

    int b1 = g_off1[n], e1 = g_off1[n + 1];
    float4 s1 = gather_dir2(g_nbr1, hv, b1, e1, lane, half, l16);
    float inv1 = 1.0f / (float)max(e1 - b1, 1);

    int b2 = g_off2[n], e2 = g_off2[n + 1];
    float4 s2 = gather_dir2(g_nbr2, hv, b2, e2, lane, half, l16);
    float inv2 = 1.0f / (float)max(e2 - b2, 1);

    // combine the two half-warp partial sums
    s1.x += __shfl_xor_sync(0xffffffffu, s1.x, 16);
    s1.y += __shfl_xor_sync(0xffffffffu, s1.y, 16);
    s1.z += __shfl_xor_sync(0xffffffffu, s1.z, 16);
    s1.w += __shfl_xor_sync(0xffffffffu, s1.w, 16);
    s2.x += __shfl_xor_sync(0xffffffffu, s2.x, 16);
    s2.y += __shfl_xor_sync(0xffffffffu, s2.y, 16);
    s2.z += __shfl_xor_sync(0xffffffffu, s2.z, 16);
    s2.w += __shfl_xor_sync(0xffffffffu, s2.w, 16);

    if (half == 0) {
        ((float4*)g_s1)[n * 16 + l16] =
            make_float4(s1.x * inv1, s1.y * inv1, s1.z * inv1, s1.w * inv1);
        ((float4*)g_s2)[n * 16 + l16] =
            make_float4(s2.x * inv2, s2.y * inv2, s2.z * inv2, s2.w * inv2);
    }
}

// ===== GEMM v4 (unchanged): thread = (node-group, col-quad) ==================
#define LT   5
#define TILE 64
#define KL   192
#define WST  68                      // w row stride (floats)
#define XST  49                      // x row stride (float4)
#define LAYER_SMEM ((KL * WST + TILE * XST * 4) * (int)sizeof(float))  // 102400

__global__ void __launch_bounds__(256) k_layer(
        const float* __restrict__ w1, const float* __restrict__ w2,
        const float* __restrict__ wr, const float* __restrict__ rb, int l) {
    extern __shared__ float sm[];
    float*  sw  = sm;                          // [192][68]
    float4* sx4 = (float4*)(sm + KL * WST);    // [64][49]
    const int tid = threadIdx.x;

    for (int s = 0; s < 3; s++) {
        const float* w = (s == 0) ? wr : (s == 1) ? w1 : w2;
        for (int i = tid; i < 64 * 64; i += 256) {
            int c = i >> 6, k = i & 63;
            sw[(s * 64 + k) * WST + c] = w[i];
        }
    }
    const int grp = tid >> 4;
    const int cq  = tid & 15;
    const float4 bias = ((const float4*)rb)[cq];
    const float4* sw4 = (const float4*)sw;

    for (int t = 0; t < LT; t++) {
        int node0 = (blockIdx.x * LT + t) * TILE;
        __syncthreads();
        for (int i4 = tid; i4 < TILE * 48; i4 += 256) {
            int nl = i4 / 48, kq = i4 % 48;
            int src = kq >> 4, k4 = kq & 15;
            int node = node0 + nl; if (node >= NN) node = NN - 1;
            const float* xp = (src == 0) ? (g_h + node * D)
                            : (src == 1) ? (g_s1 + node * D)
                                         : (g_s2 + node * D);
            sx4[nl * XST + kq] = ((const float4*)xp)[k4];
        }
        __syncthreads();

        float4 a0 = bias, a1 = bias, a2 = bias, a3 = bias;
        const float4* xr = sx4 + grp * 4 * XST;
#pragma unroll 4
        for (int kq = 0; kq < 48; kq++) {
            float4 wv0 = sw4[(4 * kq + 0) * 17 + cq];
            float4 wv1 = sw4[(4 * kq + 1) * 17 + cq];
            float4 wv2 = sw4[(4 * kq + 2) * 17 + cq];
            float4 wv3 = sw4[(4 * kq + 3) * 17 + cq];
            float4 x0 = xr[kq];
            float4 x1 = xr[XST + kq];
            float4 x2 = xr[2 * XST + kq];
            float4 x3 = xr[3 * XST + kq];
#define STEP(A, X) \
            A.x = fmaf(X.x, wv0.x, A.x); A.y = fmaf(X.x, wv0.y, A.y); \
            A.z = fmaf(X.x, wv0.z, A.z); A.w = fmaf(X.x, wv0.w, A.w); \
            A.x = fmaf(X.y, wv1.x, A.x); A.y = fmaf(X.y, wv1.y, A.y); \
            A.z = fmaf(X.y, wv1.z, A.z); A.w = fmaf(X.y, wv1.w, A.w); \
            A.x = fmaf(X.z, wv2.x, A.x); A.y = fmaf(X.z, wv2.y, A.y); \
            A.z = fmaf(X.z, wv2.z, A.z); A.w = fmaf(X.z, wv2.w, A.w); \
            A.x = fmaf(X.w, wv3.x, A.x); A.y = fmaf(X.w, wv3.y, A.y); \
            A.z = fmaf(X.w, wv3.z, A.z); A.w = fmaf(X.w, wv3.w, A.w);
            STEP(a0, x0) STEP(a1, x1) STEP(a2, x2) STEP(a3, x3)
#undef STEP
        }
        int nb = node0 + grp * 4;
        int cb = (l + 1) * D;
#define EMIT(A, I) \
        if (nb + I < NN) { \
            float4 r = make_float4(fmaxf(A.x, 0.f), fmaxf(A.y, 0.f), \
                                   fmaxf(A.z, 0.f), fmaxf(A.w, 0.f)); \
            ((float4*)(g_h + (nb + I) * D))[cq] = r; \
            ((float4*)(g_cat + (nb + I) * DCAT + cb))[cq] = r; \
        }
        EMIT(a0, 0) EMIT(a1, 1) EMIT(a2, 2) EMIT(a3, 3)
#undef EMIT
    }
}

// ===== final GEMM v4 (unchanged) =============================================
#define KF 256
#define XSTF 65
#define FINAL_SMEM ((KF * WST + TILE * XSTF * 4) * (int)sizeof(float))  // 136192

__global__ void __launch_bounds__(256) k_final(
        const float* __restrict__ fw, const float* __restrict__ fb,
        float* __restrict__ out) {
    extern __shared__ float sm[];
    float*  sw  = sm;
    float4* sx4 = (float4*)(sm + KF * WST);
    const int tid = threadIdx.x;

    for (int i = tid; i < 64 * KF; i += 256) {
        int c = i >> 8, k = i & 255;
        sw[k * WST + c] = fw[i];
    }
    const int grp = tid >> 4;
    const int cq  = tid & 15;
    const float4 bias = ((const float4*)fb)[cq];
    const float4* sw4 = (const float4*)sw;

    for (int t = 0; t < LT; t++) {
        int node0 = (blockIdx.x * LT + t) * TILE;
        __syncthreads();
        for (int i4 = tid; i4 < TILE * 64; i4 += 256) {
            int nl = i4 >> 6, kq = i4 & 63;
            int node = node0 + nl; if (node >= NN) node = NN - 1;
            sx4[nl * XSTF + kq] = ((const float4*)(g_cat + node * DCAT))[kq];
        }
        __syncthreads();

        float4 a0 = bias, a1 = bias, a2 = bias, a3 = bias;
        const float4* xr = sx4 + grp * 4 * XSTF;
#pragma unroll 4
        for (int kq = 0; kq < 64; kq++) {
            float4 wv0 = sw4[(4 * kq + 0) * 17 + cq];
            float4 wv1 = sw4[(4 * kq + 1) * 17 + cq];
            float4 wv2 = sw4[(4 * kq + 2) * 17 + cq];
            float4 wv3 = sw4[(4 * kq + 3) * 17 + cq];
            float4 x0 = xr[kq];
            float4 x1 = xr[XSTF + kq];
            float4 x2 = xr[2 * XSTF + kq];
            float4 x3 = xr[3 * XSTF + kq];
#define STEP(A, X) \
            A.x = fmaf(X.x, wv0.x, A.x); A.y = fmaf(X.x, wv0.y, A.y); \
            A.z = fmaf(X.x, wv0.z, A.z); A.w = fmaf(X.x, wv0.w, A.w); \
            A.x = fmaf(X.y, wv1.x, A.x); A.y = fmaf(X.y, wv1.y, A.y); \
            A.z = fmaf(X.y, wv1.z, A.z); A.w = fmaf(X.y, wv1.w, A.w); \
            A.x = fmaf(X.z, wv2.x, A.x); A.y = fmaf(X.z, wv2.y, A.y); \
            A.z = fmaf(X.z, wv2.z, A.z); A.w = fmaf(X.z, wv2.w, A.w); \
            A.x = fmaf(X.w, wv3.x, A.x); A.y = fmaf(X.w, wv3.y, A.y); \
            A.z = fmaf(X.w, wv3.z, A.z); A.w = fmaf(X.w, wv3.w, A.w);
            STEP(a0, x0) STEP(a1, x1) STEP(a2, x2) STEP(a3, x3)
#undef STEP
        }
        int nb = node0 + grp * 4;
        if (nb + 0 < NN) ((float4*)(out + (nb + 0) * D))[cq] = a0;
        if (nb + 1 < NN) ((float4*)(out + (nb + 1) * D))[cq] = a1;
        if (nb + 2 < NN) ((float4*)(out + (nb + 2) * D))[cq] = a2;
        if (nb + 3 < NN) ((float4*)(out + (nb + 3) * D))[cq] = a3;
    }
}

// ---------------- launch -----------------------------------------------------
extern "C" void kernel_launch(void* const* d_in, const int* in_sizes, int n_in,
                              void* d_out, int out_size) {
    const float* x     = (const float*)d_in[0];
    const int*   ei    = (const int*)d_in[1];
    const float* lin1  = (const float*)d_in[2];
    const float* lin2  = (const float*)d_in[3];
    const float* rootw = (const float*)d_in[4];
    const float* rootb = (const float*)d_in[5];
    const float* fw    = (const float*)d_in[6];
    const float* fb    = (const float*)d_in[7];
    float*       out   = (float*)d_out;

    cudaFuncSetAttribute(k_layer, cudaFuncAttributeMaxDynamicSharedMemorySize, LAYER_SMEM);
    cudaFuncSetAttribute(k_final, cudaFuncAttributeMaxDynamicSharedMemorySize, FINAL_SMEM);

    k_init <<<(NN * D + 255) / 256, 256>>>(x);
    k_count<<<(NE + 255) / 256, 256>>>(ei);
    k_scan <<<1, 1024>>>();
    k_fill <<<(NE + 255) / 256, 256>>>(ei);

    const int agg_grid  = (NN * 32 + 255) / 256;
    const int gemm_grid = (NN + LT * TILE - 1) / (LT * TILE);   // 157

    for (int l = 0; l < NL; l++) {
        k_agg  <<<agg_grid, 256>>>();
        k_layer<<<gemm_grid, 256, LAYER_SMEM>>>(lin1 + l * D * D, lin2 + l * D * D,
                                                rootw + l * D * D, rootb + l * D, l);
    }
    k_final<<<gemm_grid, 256, FINAL_SMEM>>>(fw, fb, out);
}